// round 1
// baseline (speedup 1.0000x reference)
#include <cuda_runtime.h>
#include <cuda_bf16.h>
#include <math.h>

// ---------------- problem constants ----------------
#define BSZ   8192
#define LH    20
#define NFEAT 172
#define DIM   860          // NF*3 + NF + TF
#define DHEAD 430
#define NHEAD 2
#define QKVN  2580         // 3*DIM
#define NROWS (BSZ*LH)     // 163840
#define LEF   688          // D - TF

// ---------------- scratch (__device__ globals; allocation-free) ----------------
__device__ float g_full[(size_t)NROWS * DIM];     // 563 MB
__device__ float g_qkv [(size_t)NROWS * QKVN];    // 1.69 GB
__device__ float g_cm  [(size_t)BSZ * DIM];       // ctx mean over L
__device__ float g_m   [(size_t)BSZ * DIM];       // out_proj(ctx_mean)
__device__ float g_x   [(size_t)BSZ * DIM];       // [hl | last_event_feat]
__device__ float g_h   [(size_t)BSZ * NFEAT];     // fc1 output

// ---------------- f32x2 helpers (Blackwell packed fp32, 2 FMA/instr) ----------------
__device__ __forceinline__ unsigned long long pack2(float lo, float hi) {
    unsigned long long r;
    asm("mov.b64 %0, {%1, %2};" : "=l"(r) : "f"(lo), "f"(hi));
    return r;
}
__device__ __forceinline__ void fma2(unsigned long long& d, unsigned long long a, unsigned long long b) {
    asm("fma.rn.f32x2 %0, %1, %2, %3;" : "=l"(d) : "l"(a), "l"(b), "l"(d));
}
__device__ __forceinline__ float2 unpack2(unsigned long long v) {
    float2 f;
    asm("mov.b64 {%0, %1}, %2;" : "=f"(f.x), "=f"(f.y) : "l"(v));
    return f;
}

// Accurate cos of an fp32 value (double range reduction; immune to fast-math cosf).
__device__ __forceinline__ float cos_accurate(float x) {
    double xd = (double)x;
    double q  = rint(xd * 0.15915494309189535);            // x / (2*pi)
    double r  = fma(q, -6.283185307179586476925286766559, xd);
    return cosf((float)r);                                  // |r| <= pi: accurate even under fast-math
}

// ---------------- K1: gather + time-encode -> g_full; also last_event_feat, prev_ts ----------------
__global__ void build_full_kernel(
    const int* __restrict__ nids, const int* __restrict__ hist_nids,
    const int* __restrict__ anon_ids, const int* __restrict__ hist_eids,
    const float* __restrict__ hist_ts, const int* __restrict__ hist_dirs,
    const float* __restrict__ node_emb, const float* __restrict__ edge_emb,
    const float* __restrict__ anony_emb, const float* __restrict__ time_w,
    const float* __restrict__ time_b, float* __restrict__ out_prevts)
{
    int row = blockIdx.x;
    int b = row / LH;
    int l = row - b * LH;
    int nid = nids[b];
    int hn  = hist_nids[row];
    int d   = hist_dirs[row];
    int src = d ? nid : hn;
    int dst = d ? hn  : nid;
    int aid = anon_ids[row];
    int eid = hist_eids[row];
    float tlast = hist_ts[b * LH + (LH - 1)];
    float dt = __fsub_rn(tlast, hist_ts[row]);
    bool last = (l == LH - 1);

    for (int j = threadIdx.x; j < DIM; j += blockDim.x) {
        float val;
        if (j < 172)      val = node_emb[(size_t)src * NFEAT + j];
        else if (j < 344) val = node_emb[(size_t)dst * NFEAT + (j - 172)];
        else if (j < 516) val = anony_emb[(size_t)aid * NFEAT + (j - 344)];
        else if (j < 688) val = edge_emb[(size_t)eid * NFEAT + (j - 516)];
        else {
            int jj = j - 688;
            float x = __fmul_rn(dt, time_w[jj]);   // replicate reference's fp32 rounding exactly
            x = __fadd_rn(x, time_b[jj]);
            val = cos_accurate(x);
        }
        float fv = val;
        if (last && j < LEF) {
            g_x[(size_t)b * DIM + NFEAT + j] = val;   // last_event_feat (pre-zeroing values)
            fv = 0.0f;                                 // full[:, -1, :688] = 0
        }
        g_full[(size_t)row * DIM + j] = fv;
    }
    if (last && threadIdx.x == 0) out_prevts[b] = tlast;
}

// ---------------- tiled NT GEMM: C = A(M,K) @ B(N,K)^T + bias, f32x2 inner ----------------
#define GBM 128
#define GBN 64
#define GBK 16

template<bool RELU_A, bool RELU_C>
__global__ __launch_bounds__(256) void gemm_nt(
    const float* __restrict__ A, int lda,
    const float* __restrict__ B, int ldb,
    const float* __restrict__ bias,
    float* __restrict__ C, int ldc,
    float* __restrict__ C2, int ldc2,
    int M, int N, int K)
{
    __shared__ float As[GBK][GBM + 4];
    __shared__ float Bs[GBK][GBN + 4];
    const int tid = threadIdx.x;
    const int tx = tid & 15;    // n dim
    const int ty = tid >> 4;    // m dim
    const int bm = blockIdx.y * GBM;
    const int bn = blockIdx.x * GBN;

    unsigned long long acc[4][4];
    #pragma unroll
    for (int p = 0; p < 4; p++)
        #pragma unroll
        for (int j = 0; j < 4; j++) acc[p][j] = 0ull;

    const int lr = tid >> 2;          // 0..63
    const int lc = (tid & 3) * 4;     // 0,4,8,12 (K%4==0 for all our GEMMs)

    for (int k0 = 0; k0 < K; k0 += GBK) {
        #pragma unroll
        for (int r = 0; r < 2; r++) {
            int mrow = bm + lr + r * 64;
            float4 v = make_float4(0.f, 0.f, 0.f, 0.f);
            if (mrow < M && (k0 + lc) < K)
                v = *reinterpret_cast<const float4*>(A + (size_t)mrow * lda + k0 + lc);
            if (RELU_A) {
                v.x = fmaxf(v.x, 0.f); v.y = fmaxf(v.y, 0.f);
                v.z = fmaxf(v.z, 0.f); v.w = fmaxf(v.w, 0.f);
            }
            As[lc + 0][lr + r * 64] = v.x; As[lc + 1][lr + r * 64] = v.y;
            As[lc + 2][lr + r * 64] = v.z; As[lc + 3][lr + r * 64] = v.w;
        }
        {
            int nrow = bn + lr;
            float4 v = make_float4(0.f, 0.f, 0.f, 0.f);
            if (nrow < N && (k0 + lc) < K)
                v = *reinterpret_cast<const float4*>(B + (size_t)nrow * ldb + k0 + lc);
            Bs[lc + 0][lr] = v.x; Bs[lc + 1][lr] = v.y;
            Bs[lc + 2][lr] = v.z; Bs[lc + 3][lr] = v.w;
        }
        __syncthreads();
        #pragma unroll
        for (int kk = 0; kk < GBK; kk++) {
            const unsigned long long* ap =
                reinterpret_cast<const unsigned long long*>(&As[kk][ty * 8]);
            unsigned long long a0 = ap[0], a1 = ap[1], a2 = ap[2], a3 = ap[3];
            const float4 bq = *reinterpret_cast<const float4*>(&Bs[kk][tx * 4]);
            unsigned long long b0 = pack2(bq.x, bq.x), b1 = pack2(bq.y, bq.y);
            unsigned long long b2 = pack2(bq.z, bq.z), b3 = pack2(bq.w, bq.w);
            fma2(acc[0][0], a0, b0); fma2(acc[0][1], a0, b1); fma2(acc[0][2], a0, b2); fma2(acc[0][3], a0, b3);
            fma2(acc[1][0], a1, b0); fma2(acc[1][1], a1, b1); fma2(acc[1][2], a1, b2); fma2(acc[1][3], a1, b3);
            fma2(acc[2][0], a2, b0); fma2(acc[2][1], a2, b1); fma2(acc[2][2], a2, b2); fma2(acc[2][3], a2, b3);
            fma2(acc[3][0], a3, b0); fma2(acc[3][1], a3, b1); fma2(acc[3][2], a3, b2); fma2(acc[3][3], a3, b3);
        }
        __syncthreads();
    }

    #pragma unroll
    for (int j = 0; j < 4; j++) {
        int n = bn + tx * 4 + j;
        if (n >= N) continue;
        float bv = bias[n];
        #pragma unroll
        for (int p = 0; p < 4; p++) {
            float2 c = unpack2(acc[p][j]);
            int m0 = bm + ty * 8 + 2 * p;
            float lo = c.x + bv, hi = c.y + bv;
            if (RELU_C) { lo = fmaxf(lo, 0.f); hi = fmaxf(hi, 0.f); }
            if (m0 < M) {
                C[(size_t)m0 * ldc + n] = lo;
                if (C2) C2[(size_t)m0 * ldc2 + n] = lo;
            }
            if (m0 + 1 < M) {
                C[(size_t)(m0 + 1) * ldc + n] = hi;
                if (C2) C2[(size_t)(m0 + 1) * ldc2 + n] = hi;
            }
        }
    }
}

// ---------------- K3: attention per (b, head) -> query-mean of ctx ----------------
// mean_q(ctx[b,h,q,:]) = sum_k (mean_q attn[q,k]) * v[k,:]  (out_proj deferred to GEMM2)
#define SSTR 448   // padded row stride (430 data + zero pad, 14*32 exactly)
#define ATT_SMEM ((3*LH*SSTR + LH*LH + LH + 4) * 4)

__global__ __launch_bounds__(256) void attn_mean_kernel(
    const float* __restrict__ qkv, const int* __restrict__ hist_nids,
    float* __restrict__ ctx_mean)
{
    extern __shared__ float sm[];
    float* sq = sm;
    float* sk = sq + LH * SSTR;
    float* sv = sk + LH * SSTR;
    float* sc = sv + LH * SSTR;   // 20x20 scores/attn
    float* wb = sc + LH * LH;     // 20 column means

    int b = blockIdx.x;
    int h = blockIdx.y;
    int tid = threadIdx.x;
    const float scale = (float)(1.0 / sqrt(430.0));

    size_t base = (size_t)b * LH * QKVN + (size_t)h * DHEAD;
    for (int idx = tid; idx < LH * SSTR; idx += 256) {
        int l = idx / SSTR, dd = idx - l * SSTR;
        float q = 0.f, k = 0.f, v = 0.f;
        if (dd < DHEAD) {
            size_t o = base + (size_t)l * QKVN + dd;
            q = qkv[o]; k = qkv[o + DIM]; v = qkv[o + 2 * DIM];
        }
        sq[idx] = q; sk[idx] = k; sv[idx] = v;
    }
    __syncthreads();

    int w = tid >> 5, lane = tid & 31;
    for (int qi = w; qi < LH; qi += 8) {
        float qreg[14];
        #pragma unroll
        for (int t = 0; t < 14; t++) qreg[t] = sq[qi * SSTR + lane + 32 * t];
        for (int ki = 0; ki < LH; ki++) {
            float s = 0.f;
            #pragma unroll
            for (int t = 0; t < 14; t++) s += qreg[t] * sk[ki * SSTR + lane + 32 * t];
            #pragma unroll
            for (int off = 16; off > 0; off >>= 1) s += __shfl_xor_sync(0xffffffffu, s, off);
            if (lane == 0) {
                int hn = hist_nids[b * LH + ki];
                bool masked = (hn == 0) && (ki != LH - 1);
                sc[qi * LH + ki] = masked ? -1e30f : s * scale;
            }
        }
    }
    __syncthreads();

    if (tid < LH) {  // softmax over each query row, in place
        int qi = tid;
        float mx = -1e30f;
        for (int ki = 0; ki < LH; ki++) mx = fmaxf(mx, sc[qi * LH + ki]);
        float sum = 0.f;
        for (int ki = 0; ki < LH; ki++) {
            float e = expf(sc[qi * LH + ki] - mx);
            sc[qi * LH + ki] = e;
            sum += e;
        }
        float inv = 1.f / sum;
        for (int ki = 0; ki < LH; ki++) sc[qi * LH + ki] *= inv;
    }
    __syncthreads();

    if (tid < LH) {  // column means (mean over queries)
        int ki = tid;
        float s = 0.f;
        for (int qi = 0; qi < LH; qi++) s += sc[qi * LH + ki];
        wb[ki] = s * (1.0f / LH);
    }
    __syncthreads();

    for (int dd = tid; dd < DHEAD; dd += 256) {
        float s = 0.f;
        #pragma unroll
        for (int ki = 0; ki < LH; ki++) s += wb[ki] * sv[ki * SSTR + dd];
        ctx_mean[(size_t)b * DIM + (size_t)h * DHEAD + dd] = s;
    }
}

// ---------------- host ----------------
extern "C" void kernel_launch(void* const* d_in, const int* in_sizes, int n_in,
                              void* d_out, int out_size)
{
    const int*   nids       = (const int*)  d_in[0];
    const int*   hist_nids  = (const int*)  d_in[1];
    const int*   anon_ids   = (const int*)  d_in[2];
    const int*   hist_eids  = (const int*)  d_in[3];
    const float* hist_ts    = (const float*)d_in[4];
    const int*   hist_dirs  = (const int*)  d_in[5];
    const float* node_emb   = (const float*)d_in[6];
    const float* edge_emb   = (const float*)d_in[7];
    const float* anony_emb  = (const float*)d_in[8];
    const float* time_w     = (const float*)d_in[9];
    const float* time_b     = (const float*)d_in[10];
    const float* in_proj_w  = (const float*)d_in[11];
    const float* in_proj_b  = (const float*)d_in[12];
    const float* out_proj_w = (const float*)d_in[13];
    const float* out_proj_b = (const float*)d_in[14];
    const float* outfn_w    = (const float*)d_in[15];
    const float* outfn_b    = (const float*)d_in[16];
    const float* fc1_w      = (const float*)d_in[17];
    const float* fc1_b      = (const float*)d_in[18];
    const float* fc2_w      = (const float*)d_in[19];
    const float* fc2_b      = (const float*)d_in[20];

    float* out     = (float*)d_out;
    float* out_hl  = out;
    float* out_hr  = out + (size_t)BSZ * NFEAT;
    float* out_pts = out + (size_t)2 * BSZ * NFEAT;

    float *full, *qkv, *cm, *mbuf, *xbuf, *hbuf;
    cudaGetSymbolAddress((void**)&full, g_full);
    cudaGetSymbolAddress((void**)&qkv,  g_qkv);
    cudaGetSymbolAddress((void**)&cm,   g_cm);
    cudaGetSymbolAddress((void**)&mbuf, g_m);
    cudaGetSymbolAddress((void**)&xbuf, g_x);
    cudaGetSymbolAddress((void**)&hbuf, g_h);

    cudaFuncSetAttribute(attn_mean_kernel,
                         cudaFuncAttributeMaxDynamicSharedMemorySize, ATT_SMEM);

    // K1: build full + last_event_feat + prev_ts
    build_full_kernel<<<NROWS, 128>>>(nids, hist_nids, anon_ids, hist_eids, hist_ts,
                                      hist_dirs, node_emb, edge_emb, anony_emb,
                                      time_w, time_b, out_pts);

    // K2: qkv = full @ in_proj_w^T + b      (M=163840, N=2580, K=860)
    {
        dim3 grid((QKVN + GBN - 1) / GBN, NROWS / GBM);
        gemm_nt<false, false><<<grid, 256>>>(full, DIM, in_proj_w, DIM, in_proj_b,
                                             qkv, QKVN, (float*)nullptr, 0,
                                             NROWS, QKVN, DIM);
    }

    // K3: attention -> ctx mean over L
    attn_mean_kernel<<<dim3(BSZ, NHEAD), 256, ATT_SMEM>>>(qkv, hist_nids, cm);

    // K4: m = ctx_mean @ out_proj_w^T + b   (M=8192, N=860, K=860)
    {
        dim3 grid((DIM + GBN - 1) / GBN, BSZ / GBM);
        gemm_nt<false, false><<<grid, 256>>>(cm, DIM, out_proj_w, DIM, out_proj_b,
                                             mbuf, DIM, (float*)nullptr, 0,
                                             BSZ, DIM, DIM);
    }

    // K5: hl = relu(m) @ outfn_w^T + b -> d_out AND x[:, :172]   (N=172, K=860)
    {
        dim3 grid((NFEAT + GBN - 1) / GBN, BSZ / GBM);
        gemm_nt<true, false><<<grid, 256>>>(mbuf, DIM, outfn_w, DIM, outfn_b,
                                            out_hl, NFEAT, xbuf, DIM,
                                            BSZ, NFEAT, DIM);
    }

    // K6: h = relu(x @ fc1_w^T + b)          (N=172, K=860)
    {
        dim3 grid((NFEAT + GBN - 1) / GBN, BSZ / GBM);
        gemm_nt<false, true><<<grid, 256>>>(xbuf, DIM, fc1_w, DIM, fc1_b,
                                            hbuf, NFEAT, (float*)nullptr, 0,
                                            BSZ, NFEAT, DIM);
    }

    // K7: hr = h @ fc2_w^T + b -> d_out      (N=172, K=172)
    {
        dim3 grid((NFEAT + GBN - 1) / GBN, BSZ / GBM);
        gemm_nt<false, false><<<grid, 256>>>(hbuf, NFEAT, fc2_w, NFEAT, fc2_b,
                                             out_hr, NFEAT, (float*)nullptr, 0,
                                             BSZ, NFEAT, NFEAT);
    }
}

// round 4
// speedup vs baseline: 2.6550x; 2.6550x over previous
#include <cuda_runtime.h>
#include <cuda_bf16.h>
#include <math.h>
#include <stdint.h>

// ---------------- problem constants ----------------
#define BSZ   8192
#define LH    20
#define NFEAT 172
#define DIM   860
#define DHEAD 430
#define NHEAD 2
#define QKVN  2580
#define NROWS (BSZ*LH)      // 163840
#define LEF   688
#define KP2   704           // reduced K (no anony block) padded: 11*64
#define NC    (KP2/64)      // 11 k-chunks
#define NPAD2 2688          // 21*128

// ---------------- scratch ----------------
__device__ __nv_bfloat16 g_ahi[(size_t)NROWS * KP2];
__device__ __nv_bfloat16 g_alo[(size_t)NROWS * KP2];
__device__ __nv_bfloat16 g_bhi[(size_t)NPAD2 * KP2];
__device__ __nv_bfloat16 g_blo[(size_t)NPAD2 * KP2];
__device__ float g_aq [(size_t)(LH + 1) * QKVN];   // anony_emb @ W_anony^T
__device__ float g_qkv[(size_t)NROWS * QKVN];
__device__ float g_cm [(size_t)BSZ * DIM];
__device__ float g_m  [(size_t)BSZ * DIM];
__device__ float g_x  [(size_t)BSZ * DIM];
__device__ float g_h  [(size_t)BSZ * NFEAT];

// ---------------- helpers ----------------
__device__ __forceinline__ uint32_t smem_u32(const void* p) {
    uint32_t a;
    asm("{ .reg .u64 t; cvta.to.shared.u64 t, %1; cvt.u32.u64 %0, t; }" : "=r"(a) : "l"(p));
    return a;
}
__device__ __forceinline__ void cpa16(uint32_t s, const void* g) {
    asm volatile("cp.async.cg.shared.global [%0], [%1], 16;" :: "r"(s), "l"(g));
}
#define CP_COMMIT() asm volatile("cp.async.commit_group;" ::: "memory")
#define CP_WAIT1()  asm volatile("cp.async.wait_group 1;" ::: "memory")

#define LDSM4(r, addr) \
    asm volatile("ldmatrix.sync.aligned.m8n8.x4.shared.b16 {%0,%1,%2,%3}, [%4];" \
        : "=r"((r)[0]), "=r"((r)[1]), "=r"((r)[2]), "=r"((r)[3]) : "r"(addr) : "memory")
#define MMA_BF16(acc, a, b0, b1) \
    asm volatile("mma.sync.aligned.m16n8k16.row.col.f32.bf16.bf16.f32 " \
        "{%0,%1,%2,%3}, {%4,%5,%6,%7}, {%8,%9}, {%0,%1,%2,%3};" \
        : "+f"((acc)[0]), "+f"((acc)[1]), "+f"((acc)[2]), "+f"((acc)[3]) \
        : "r"((a)[0]), "r"((a)[1]), "r"((a)[2]), "r"((a)[3]), "r"(b0), "r"(b1))

__device__ __forceinline__ float cos_accurate(float x) {
    double xd = (double)x;
    double q  = rint(xd * 0.15915494309189535);
    double r  = fma(q, -6.283185307179586476925286766559, xd);
    return cosf((float)r);
}
__device__ __forceinline__ void split_bf16(float v, __nv_bfloat16& h, __nv_bfloat16& l) {
    h = __float2bfloat16_rn(v);
    l = __float2bfloat16_rn(v - __bfloat162float(h));
}
__device__ __forceinline__ unsigned long long pack2(float lo, float hi) {
    unsigned long long r;
    asm("mov.b64 %0, {%1, %2};" : "=l"(r) : "f"(lo), "f"(hi));
    return r;
}
__device__ __forceinline__ void fma2(unsigned long long& d, unsigned long long a, unsigned long long b) {
    asm("fma.rn.f32x2 %0, %1, %2, %3;" : "=l"(d) : "l"(a), "l"(b), "l"(d));
}
__device__ __forceinline__ float2 unpack2(unsigned long long v) {
    float2 f;
    asm("mov.b64 {%0, %1}, %2;" : "=f"(f.x), "=f"(f.y) : "l"(v));
    return f;
}

// ---------------- K1: gather + time-encode -> bf16 hi/lo A (no anony block) ----------------
// new K layout: [0,172) src | [172,344) dst | [344,516) edge | [516,688) ts | [688,704) pad
__global__ void build_full_kernel(
    const int* __restrict__ nids, const int* __restrict__ hist_nids,
    const int* __restrict__ anon_ids, const int* __restrict__ hist_eids,
    const float* __restrict__ hist_ts, const int* __restrict__ hist_dirs,
    const float* __restrict__ node_emb, const float* __restrict__ edge_emb,
    const float* __restrict__ anony_emb, const float* __restrict__ time_w,
    const float* __restrict__ time_b, float* __restrict__ out_prevts)
{
    int row = blockIdx.x;
    int b = row / LH;
    int l = row - b * LH;
    int nid = nids[b];
    int hn  = hist_nids[row];
    int d   = hist_dirs[row];
    int src = d ? nid : hn;
    int dst = d ? hn  : nid;
    int aid = anon_ids[row];
    int eid = hist_eids[row];
    float tlast = hist_ts[b * LH + (LH - 1)];
    float dt = __fsub_rn(tlast, hist_ts[row]);
    bool last = (l == LH - 1);

    for (int j = threadIdx.x; j < KP2; j += blockDim.x) {
        float val = 0.0f;
        if (j < 172)      val = node_emb[(size_t)src * NFEAT + j];
        else if (j < 344) val = node_emb[(size_t)dst * NFEAT + (j - 172)];
        else if (j < 516) val = edge_emb[(size_t)eid * NFEAT + (j - 344)];
        else if (j < 688) {
            int jj = j - 516;
            float x = __fmul_rn(dt, time_w[jj]);
            x = __fadd_rn(x, time_b[jj]);
            val = cos_accurate(x);
        }
        if (last && j < 516) {
            // last_event_feat (original order: src, dst, anony, edge)
            int xo = (j < 344) ? (NFEAT + j) : (NFEAT + j + NFEAT);  // edge shifts past anony
            g_x[(size_t)b * DIM + xo] = val;
            val = 0.0f;
        }
        __nv_bfloat16 h, lo;
        split_bf16(val, h, lo);
        g_ahi[(size_t)row * KP2 + j] = h;
        g_alo[(size_t)row * KP2 + j] = lo;
    }
    if (last) {
        for (int j = threadIdx.x; j < NFEAT; j += blockDim.x)
            g_x[(size_t)b * DIM + NFEAT + 344 + j] = anony_emb[(size_t)aid * NFEAT + j];
        if (threadIdx.x == 0) out_prevts[b] = tlast;
    }
}

// ---------------- K1b: split in_proj_w (minus anony cols) into padded bf16 hi/lo ----------------
__global__ void split_b_kernel(const float* __restrict__ W)
{
    size_t idx = (size_t)blockIdx.x * blockDim.x + threadIdx.x;
    if (idx >= (size_t)NPAD2 * KP2) return;
    int r = (int)(idx / KP2);
    int k = (int)(idx - (size_t)r * KP2);
    float v = 0.0f;
    if (r < QKVN) {
        if (k < 344)      v = W[(size_t)r * DIM + k];
        else if (k < 688) v = W[(size_t)r * DIM + k + NFEAT];   // skip anony cols [344,516)
    }
    __nv_bfloat16 h, lo;
    split_bf16(v, h, lo);
    g_bhi[idx] = h;
    g_blo[idx] = lo;
}

// ---------------- K1c: AQ = anony_emb @ W[:,344:516]^T  (21 x 2580, fp32 exact) ----------------
__global__ void anony_proj_kernel(const float* __restrict__ anony_emb,
                                  const float* __restrict__ W)
{
    int n = blockIdx.x * blockDim.x + threadIdx.x;
    int a = blockIdx.y;
    if (n >= QKVN) return;
    float s = 0.0f;
    const float* wr = W + (size_t)n * DIM + 344;
    const float* ar = anony_emb + (size_t)a * NFEAT;
    #pragma unroll 4
    for (int k = 0; k < NFEAT; k++) s += ar[k] * wr[k];
    g_aq[(size_t)a * QKVN + n] = s;
}

// ---------------- K2: qkv GEMM via mma.sync bf16 x3 (error-compensated) ----------------
// CTA tile 128x128, BK=64, 3-stage cp.async pipeline.
#define QSM_STAGE 65536
#define QSM_TOTAL (3*QSM_STAGE)

__device__ __forceinline__ void qkv_load_stage(
    uint32_t sb, int stage, int c, int bm, int bn, int tid,
    const __nv_bfloat16* Ahi, const __nv_bfloat16* Alo,
    const __nv_bfloat16* Bhi, const __nv_bfloat16* Blo)
{
    uint32_t sbase = sb + stage * QSM_STAGE;
    const size_t kof = (size_t)c * 64;
    #pragma unroll
    for (int it = 0; it < 4; it++) {
        int cid = tid + it * 256;          // 0..1023
        int r  = cid >> 3;
        int kc = cid & 7;
        uint32_t soff = (uint32_t)(r * 128 + ((kc ^ (r & 7)) << 4));
        const char* gah = (const char*)(Ahi + (size_t)(bm + r) * KP2 + kof) + kc * 16;
        const char* gal = (const char*)(Alo + (size_t)(bm + r) * KP2 + kof) + kc * 16;
        const char* gbh = (const char*)(Bhi + (size_t)(bn + r) * KP2 + kof) + kc * 16;
        const char* gbl = (const char*)(Blo + (size_t)(bn + r) * KP2 + kof) + kc * 16;
        cpa16(sbase +         soff, gah);
        cpa16(sbase + 16384 + soff, gal);
        cpa16(sbase + 32768 + soff, gbh);
        cpa16(sbase + 49152 + soff, gbl);
    }
    CP_COMMIT();
}

__global__ __launch_bounds__(256) void qkv_mma_kernel(
    const __nv_bfloat16* __restrict__ Ahi, const __nv_bfloat16* __restrict__ Alo,
    const __nv_bfloat16* __restrict__ Bhi, const __nv_bfloat16* __restrict__ Blo,
    const float* __restrict__ bias, const float* __restrict__ AQ,
    const int* __restrict__ anon_ids, float* __restrict__ C)
{
    extern __shared__ char smem[];
    const uint32_t sb = smem_u32(smem);
    const int tid = threadIdx.x;
    const int wid = tid >> 5;
    const int lane = tid & 31;
    const int warp_m = wid >> 2;       // 0..1 -> 64 rows each
    const int warp_n = wid & 3;        // 0..3 -> 32 cols each
    const int bm = blockIdx.y * 128;
    const int bn = blockIdx.x * 128;

    float acc[4][4][4];
    #pragma unroll
    for (int mi = 0; mi < 4; mi++)
        #pragma unroll
        for (int nf = 0; nf < 4; nf++)
            #pragma unroll
            for (int t = 0; t < 4; t++) acc[mi][nf][t] = 0.0f;

    qkv_load_stage(sb, 0, 0, bm, bn, tid, Ahi, Alo, Bhi, Blo);
    qkv_load_stage(sb, 1, 1, bm, bn, tid, Ahi, Alo, Bhi, Blo);

    for (int c = 0; c < NC; c++) {
        const int stage = c % 3;
        CP_WAIT1();
        __syncthreads();
        if (c + 2 < NC)
            qkv_load_stage(sb, (c + 2) % 3, c + 2, bm, bn, tid, Ahi, Alo, Bhi, Blo);

        const uint32_t sA = sb + stage * QSM_STAGE;
        const uint32_t sB = sA + 32768;
        #pragma unroll
        for (int kk = 0; kk < 4; kk++) {
            uint32_t ah[4][4], al[4][4];
            #pragma unroll
            for (int mi = 0; mi < 4; mi++) {
                int mrow = warp_m * 64 + mi * 16 + (lane & 15);
                int chunk = kk * 2 + (lane >> 4);
                uint32_t addr = sA + mrow * 128 + ((chunk ^ (mrow & 7)) << 4);
                LDSM4(ah[mi], addr);
                LDSM4(al[mi], addr + 16384);
            }
            // B fragments: NON-trans ldmatrix on [n][k] row-major smem.
            // matrix0 = n[0:8) k-lo (b0), matrix1 = n[0:8) k-hi (b1),
            // matrix2 = n[8:16) k-lo, matrix3 = n[8:16) k-hi.
            uint32_t bh[2][4], bl[2][4];
            #pragma unroll
            for (int np = 0; np < 2; np++) {
                int nrow = warp_n * 32 + np * 16 + ((lane >> 4) << 3) + (lane & 7);
                int chunk = kk * 2 + ((lane >> 3) & 1);
                uint32_t addr = sB + nrow * 128 + ((chunk ^ (nrow & 7)) << 4);
                LDSM4(bh[np], addr);
                LDSM4(bl[np], addr + 16384);
            }
            #pragma unroll
            for (int mi = 0; mi < 4; mi++) {
                #pragma unroll
                for (int nf = 0; nf < 4; nf++) {
                    int np = nf >> 1, ri = (nf & 1) * 2;
                    MMA_BF16(acc[mi][nf], ah[mi], bh[np][ri], bh[np][ri + 1]);
                    MMA_BF16(acc[mi][nf], al[mi], bh[np][ri], bh[np][ri + 1]);
                    MMA_BF16(acc[mi][nf], ah[mi], bl[np][ri], bl[np][ri + 1]);
                }
            }
        }
    }

    // epilogue: + bias + anony gather (zero for last row of each sequence)
    const int group = lane >> 2;
    const int tc2 = (lane & 3) * 2;
    #pragma unroll
    for (int mi = 0; mi < 4; mi++) {
        int r0 = bm + warp_m * 64 + mi * 16 + group;
        int r1 = r0 + 8;
        int aid0 = anon_ids[r0];
        int aid1 = anon_ids[r1];
        bool nl0 = (r0 % LH) != (LH - 1);
        bool nl1 = (r1 % LH) != (LH - 1);
        #pragma unroll
        for (int nf = 0; nf < 4; nf++) {
            int n = bn + warp_n * 32 + nf * 8 + tc2;
            if (n >= QKVN) continue;
            float2 bv = *(const float2*)(bias + n);
            float2 o0, o1;
            o0.x = acc[mi][nf][0] + bv.x;
            o0.y = acc[mi][nf][1] + bv.y;
            o1.x = acc[mi][nf][2] + bv.x;
            o1.y = acc[mi][nf][3] + bv.y;
            if (nl0) {
                float2 q = *(const float2*)(AQ + (size_t)aid0 * QKVN + n);
                o0.x += q.x; o0.y += q.y;
            }
            if (nl1) {
                float2 q = *(const float2*)(AQ + (size_t)aid1 * QKVN + n);
                o1.x += q.x; o1.y += q.y;
            }
            *(float2*)(C + (size_t)r0 * QKVN + n) = o0;
            *(float2*)(C + (size_t)r1 * QKVN + n) = o1;
        }
    }
}

// ---------------- small-GEMM path (f32x2 SIMT) for K4-K7 ----------------
#define GBM 128
#define GBN 64
#define GBK 16

template<bool RELU_A, bool RELU_C>
__global__ __launch_bounds__(256) void gemm_nt(
    const float* __restrict__ A, int lda,
    const float* __restrict__ B, int ldb,
    const float* __restrict__ bias,
    float* __restrict__ C, int ldc,
    float* __restrict__ C2, int ldc2,
    int M, int N, int K)
{
    __shared__ float As[GBK][GBM + 4];
    __shared__ float Bs[GBK][GBN + 4];
    const int tid = threadIdx.x;
    const int tx = tid & 15;
    const int ty = tid >> 4;
    const int bm = blockIdx.y * GBM;
    const int bn = blockIdx.x * GBN;

    unsigned long long acc[4][4];
    #pragma unroll
    for (int p = 0; p < 4; p++)
        #pragma unroll
        for (int j = 0; j < 4; j++) acc[p][j] = 0ull;

    const int lr = tid >> 2;
    const int lc = (tid & 3) * 4;

    for (int k0 = 0; k0 < K; k0 += GBK) {
        #pragma unroll
        for (int r = 0; r < 2; r++) {
            int mrow = bm + lr + r * 64;
            float4 v = make_float4(0.f, 0.f, 0.f, 0.f);
            if (mrow < M && (k0 + lc) < K)
                v = *reinterpret_cast<const float4*>(A + (size_t)mrow * lda + k0 + lc);
            if (RELU_A) {
                v.x = fmaxf(v.x, 0.f); v.y = fmaxf(v.y, 0.f);
                v.z = fmaxf(v.z, 0.f); v.w = fmaxf(v.w, 0.f);
            }
            As[lc + 0][lr + r * 64] = v.x; As[lc + 1][lr + r * 64] = v.y;
            As[lc + 2][lr + r * 64] = v.z; As[lc + 3][lr + r * 64] = v.w;
        }
        {
            int nrow = bn + lr;
            float4 v = make_float4(0.f, 0.f, 0.f, 0.f);
            if (nrow < N && (k0 + lc) < K)
                v = *reinterpret_cast<const float4*>(B + (size_t)nrow * ldb + k0 + lc);
            Bs[lc + 0][lr] = v.x; Bs[lc + 1][lr] = v.y;
            Bs[lc + 2][lr] = v.z; Bs[lc + 3][lr] = v.w;
        }
        __syncthreads();
        #pragma unroll
        for (int kk = 0; kk < GBK; kk++) {
            const unsigned long long* ap =
                reinterpret_cast<const unsigned long long*>(&As[kk][ty * 8]);
            unsigned long long a0 = ap[0], a1 = ap[1], a2 = ap[2], a3 = ap[3];
            const float4 bq = *reinterpret_cast<const float4*>(&Bs[kk][tx * 4]);
            unsigned long long b0 = pack2(bq.x, bq.x), b1 = pack2(bq.y, bq.y);
            unsigned long long b2 = pack2(bq.z, bq.z), b3 = pack2(bq.w, bq.w);
            fma2(acc[0][0], a0, b0); fma2(acc[0][1], a0, b1); fma2(acc[0][2], a0, b2); fma2(acc[0][3], a0, b3);
            fma2(acc[1][0], a1, b0); fma2(acc[1][1], a1, b1); fma2(acc[1][2], a1, b2); fma2(acc[1][3], a1, b3);
            fma2(acc[2][0], a2, b0); fma2(acc[2][1], a2, b1); fma2(acc[2][2], a2, b2); fma2(acc[2][3], a2, b3);
            fma2(acc[3][0], a3, b0); fma2(acc[3][1], a3, b1); fma2(acc[3][2], a3, b2); fma2(acc[3][3], a3, b3);
        }
        __syncthreads();
    }

    #pragma unroll
    for (int j = 0; j < 4; j++) {
        int n = bn + tx * 4 + j;
        if (n >= N) continue;
        float bv = bias[n];
        #pragma unroll
        for (int p = 0; p < 4; p++) {
            float2 cc = unpack2(acc[p][j]);
            int m0 = bm + ty * 8 + 2 * p;
            float lo = cc.x + bv, hi = cc.y + bv;
            if (RELU_C) { lo = fmaxf(lo, 0.f); hi = fmaxf(hi, 0.f); }
            if (m0 < M) {
                C[(size_t)m0 * ldc + n] = lo;
                if (C2) C2[(size_t)m0 * ldc2 + n] = lo;
            }
            if (m0 + 1 < M) {
                C[(size_t)(m0 + 1) * ldc + n] = hi;
                if (C2) C2[(size_t)(m0 + 1) * ldc2 + n] = hi;
            }
        }
    }
}

// ---------------- K3: attention per (b, head) -> query-mean of ctx ----------------
#define SSTR 448
#define ATT_SMEM ((3*LH*SSTR + LH*LH + LH + 4) * 4)

__global__ __launch_bounds__(256) void attn_mean_kernel(
    const float* __restrict__ qkv, const int* __restrict__ hist_nids,
    float* __restrict__ ctx_mean)
{
    extern __shared__ float sm[];
    float* sq = sm;
    float* sk = sq + LH * SSTR;
    float* sv = sk + LH * SSTR;
    float* sc = sv + LH * SSTR;
    float* wb = sc + LH * LH;

    int b = blockIdx.x;
    int h = blockIdx.y;
    int tid = threadIdx.x;
    const float scale = (float)(1.0 / sqrt(430.0));

    size_t base = (size_t)b * LH * QKVN + (size_t)h * DHEAD;
    for (int idx = tid; idx < LH * SSTR; idx += 256) {
        int l = idx / SSTR, dd = idx - l * SSTR;
        float q = 0.f, k = 0.f, v = 0.f;
        if (dd < DHEAD) {
            size_t o = base + (size_t)l * QKVN + dd;
            q = qkv[o]; k = qkv[o + DIM]; v = qkv[o + 2 * DIM];
        }
        sq[idx] = q; sk[idx] = k; sv[idx] = v;
    }
    __syncthreads();

    int w = tid >> 5, lane = tid & 31;
    for (int qi = w; qi < LH; qi += 8) {
        float qreg[14];
        #pragma unroll
        for (int t = 0; t < 14; t++) qreg[t] = sq[qi * SSTR + lane + 32 * t];
        for (int ki = 0; ki < LH; ki++) {
            float s = 0.f;
            #pragma unroll
            for (int t = 0; t < 14; t++) s += qreg[t] * sk[ki * SSTR + lane + 32 * t];
            #pragma unroll
            for (int off = 16; off > 0; off >>= 1) s += __shfl_xor_sync(0xffffffffu, s, off);
            if (lane == 0) {
                int hn = hist_nids[b * LH + ki];
                bool masked = (hn == 0) && (ki != LH - 1);
                sc[qi * LH + ki] = masked ? -1e30f : s * scale;
            }
        }
    }
    __syncthreads();

    if (tid < LH) {
        int qi = tid;
        float mx = -1e30f;
        for (int ki = 0; ki < LH; ki++) mx = fmaxf(mx, sc[qi * LH + ki]);
        float sum = 0.f;
        for (int ki = 0; ki < LH; ki++) {
            float e = expf(sc[qi * LH + ki] - mx);
            sc[qi * LH + ki] = e;
            sum += e;
        }
        float inv = 1.f / sum;
        for (int ki = 0; ki < LH; ki++) sc[qi * LH + ki] *= inv;
    }
    __syncthreads();

    if (tid < LH) {
        int ki = tid;
        float s = 0.f;
        for (int qi = 0; qi < LH; qi++) s += sc[qi * LH + ki];
        wb[ki] = s * (1.0f / LH);
    }
    __syncthreads();

    for (int dd = tid; dd < DHEAD; dd += 256) {
        float s = 0.f;
        #pragma unroll
        for (int ki = 0; ki < LH; ki++) s += wb[ki] * sv[ki * SSTR + dd];
        ctx_mean[(size_t)b * DIM + (size_t)h * DHEAD + dd] = s;
    }
}

// ---------------- host ----------------
extern "C" void kernel_launch(void* const* d_in, const int* in_sizes, int n_in,
                              void* d_out, int out_size)
{
    const int*   nids       = (const int*)  d_in[0];
    const int*   hist_nids  = (const int*)  d_in[1];
    const int*   anon_ids   = (const int*)  d_in[2];
    const int*   hist_eids  = (const int*)  d_in[3];
    const float* hist_ts    = (const float*)d_in[4];
    const int*   hist_dirs  = (const int*)  d_in[5];
    const float* node_emb   = (const float*)d_in[6];
    const float* edge_emb   = (const float*)d_in[7];
    const float* anony_emb  = (const float*)d_in[8];
    const float* time_w     = (const float*)d_in[9];
    const float* time_b     = (const float*)d_in[10];
    const float* in_proj_w  = (const float*)d_in[11];
    const float* in_proj_b  = (const float*)d_in[12];
    const float* out_proj_w = (const float*)d_in[13];
    const float* out_proj_b = (const float*)d_in[14];
    const float* outfn_w    = (const float*)d_in[15];
    const float* outfn_b    = (const float*)d_in[16];
    const float* fc1_w      = (const float*)d_in[17];
    const float* fc1_b      = (const float*)d_in[18];
    const float* fc2_w      = (const float*)d_in[19];
    const float* fc2_b      = (const float*)d_in[20];

    float* out     = (float*)d_out;
    float* out_hl  = out;
    float* out_hr  = out + (size_t)BSZ * NFEAT;
    float* out_pts = out + (size_t)2 * BSZ * NFEAT;

    __nv_bfloat16 *ahi, *alo, *bhi, *blo;
    float *aq, *qkv, *cm, *mbuf, *xbuf, *hbuf;
    cudaGetSymbolAddress((void**)&ahi, g_ahi);
    cudaGetSymbolAddress((void**)&alo, g_alo);
    cudaGetSymbolAddress((void**)&bhi, g_bhi);
    cudaGetSymbolAddress((void**)&blo, g_blo);
    cudaGetSymbolAddress((void**)&aq,  g_aq);
    cudaGetSymbolAddress((void**)&qkv, g_qkv);
    cudaGetSymbolAddress((void**)&cm,  g_cm);
    cudaGetSymbolAddress((void**)&mbuf, g_m);
    cudaGetSymbolAddress((void**)&xbuf, g_x);
    cudaGetSymbolAddress((void**)&hbuf, g_h);

    cudaFuncSetAttribute(attn_mean_kernel,
                         cudaFuncAttributeMaxDynamicSharedMemorySize, ATT_SMEM);
    cudaFuncSetAttribute(qkv_mma_kernel,
                         cudaFuncAttributeMaxDynamicSharedMemorySize, QSM_TOTAL);

    // K1 family: build operands
    build_full_kernel<<<NROWS, 128>>>(nids, hist_nids, anon_ids, hist_eids, hist_ts,
                                      hist_dirs, node_emb, edge_emb, anony_emb,
                                      time_w, time_b, out_pts);
    {
        size_t tot = (size_t)NPAD2 * KP2;
        split_b_kernel<<<(int)((tot + 255) / 256), 256>>>(in_proj_w);
    }
    anony_proj_kernel<<<dim3((QKVN + 255) / 256, LH + 1), 256>>>(anony_emb, in_proj_w);

    // K2: qkv GEMM on mma.sync tensor path
    {
        dim3 grid(NPAD2 / 128, NROWS / 128);
        qkv_mma_kernel<<<grid, 256, QSM_TOTAL>>>(ahi, alo, bhi, blo, in_proj_b,
                                                 aq, anon_ids, qkv);
    }

    // K3: attention -> ctx mean over L
    attn_mean_kernel<<<dim3(BSZ, NHEAD), 256, ATT_SMEM>>>(qkv, hist_nids, cm);

    // K4: m = ctx_mean @ out_proj_w^T + b
    {
        dim3 grid((DIM + GBN - 1) / GBN, BSZ / GBM);
        gemm_nt<false, false><<<grid, 256>>>(cm, DIM, out_proj_w, DIM, out_proj_b,
                                             mbuf, DIM, (float*)nullptr, 0,
                                             BSZ, DIM, DIM);
    }
    // K5: hl = relu(m) @ outfn_w^T + b -> d_out AND x[:, :172]
    {
        dim3 grid((NFEAT + GBN - 1) / GBN, BSZ / GBM);
        gemm_nt<true, false><<<grid, 256>>>(mbuf, DIM, outfn_w, DIM, outfn_b,
                                            out_hl, NFEAT, xbuf, DIM,
                                            BSZ, NFEAT, DIM);
    }
    // K6: h = relu(x @ fc1_w^T + b)
    {
        dim3 grid((NFEAT + GBN - 1) / GBN, BSZ / GBM);
        gemm_nt<false, true><<<grid, 256>>>(xbuf, DIM, fc1_w, DIM, fc1_b,
                                            hbuf, NFEAT, (float*)nullptr, 0,
                                            BSZ, NFEAT, DIM);
    }
    // K7: hr = h @ fc2_w^T + b -> d_out
    {
        dim3 grid((NFEAT + GBN - 1) / GBN, BSZ / GBM);
        gemm_nt<false, false><<<grid, 256>>>(hbuf, NFEAT, fc2_w, NFEAT, fc2_b,
                                             out_hr, NFEAT, (float*)nullptr, 0,
                                             BSZ, NFEAT, NFEAT);
    }
}

// round 5
// speedup vs baseline: 4.7957x; 1.8063x over previous
#include <cuda_runtime.h>
#include <cuda_bf16.h>
#include <cuda_fp16.h>
#include <math.h>
#include <stdint.h>

// ---------------- problem constants ----------------
#define BSZ   8192
#define LH    20
#define NFEAT 172
#define DIM   860
#define DHEAD 430
#define NHEAD 2
#define QKVN  2580
#define NROWS (BSZ*LH)      // 163840
#define LEF   688
#define KP2   704           // reduced K (no anony block) padded: 11*64
#define NC    (KP2/64)      // 11 k-chunks
#define NPAD2 2688          // 21*128

// ---------------- scratch ----------------
__device__ __half g_a[(size_t)NROWS * KP2];        // fp16 activations (no anony block)
__device__ __half g_b[(size_t)NPAD2 * KP2];        // fp16 weights
__device__ float g_aq [(size_t)(LH + 1) * QKVN];   // anony_emb @ W_anony^T (fp32 exact)
__device__ float g_qkv[(size_t)NROWS * QKVN];
__device__ float g_cm [(size_t)BSZ * DIM];
__device__ float g_m  [(size_t)BSZ * DIM];
__device__ float g_x  [(size_t)BSZ * DIM];
__device__ float g_h  [(size_t)BSZ * NFEAT];

// ---------------- helpers ----------------
__device__ __forceinline__ uint32_t smem_u32(const void* p) {
    uint32_t a;
    asm("{ .reg .u64 t; cvta.to.shared.u64 t, %1; cvt.u32.u64 %0, t; }" : "=r"(a) : "l"(p));
    return a;
}
__device__ __forceinline__ void cpa16(uint32_t s, const void* g) {
    asm volatile("cp.async.cg.shared.global [%0], [%1], 16;" :: "r"(s), "l"(g));
}
#define CP_COMMIT() asm volatile("cp.async.commit_group;" ::: "memory")
#define CP_WAIT1()  asm volatile("cp.async.wait_group 1;" ::: "memory")

#define LDSM4(r, addr) \
    asm volatile("ldmatrix.sync.aligned.m8n8.x4.shared.b16 {%0,%1,%2,%3}, [%4];" \
        : "=r"((r)[0]), "=r"((r)[1]), "=r"((r)[2]), "=r"((r)[3]) : "r"(addr) : "memory")
#define MMA_F16(acc, a, b0, b1) \
    asm volatile("mma.sync.aligned.m16n8k16.row.col.f32.f16.f16.f32 " \
        "{%0,%1,%2,%3}, {%4,%5,%6,%7}, {%8,%9}, {%0,%1,%2,%3};" \
        : "+f"((acc)[0]), "+f"((acc)[1]), "+f"((acc)[2]), "+f"((acc)[3]) \
        : "r"((a)[0]), "r"((a)[1]), "r"((a)[2]), "r"((a)[3]), "r"(b0), "r"(b1))

__device__ __forceinline__ float cos_accurate(float x) {
    double xd = (double)x;
    double q  = rint(xd * 0.15915494309189535);
    double r  = fma(q, -6.283185307179586476925286766559, xd);
    return cosf((float)r);
}
__device__ __forceinline__ unsigned long long pack2(float lo, float hi) {
    unsigned long long r;
    asm("mov.b64 %0, {%1, %2};" : "=l"(r) : "f"(lo), "f"(hi));
    return r;
}
__device__ __forceinline__ void fma2(unsigned long long& d, unsigned long long a, unsigned long long b) {
    asm("fma.rn.f32x2 %0, %1, %2, %3;" : "=l"(d) : "l"(a), "l"(b), "l"(d));
}
__device__ __forceinline__ float2 unpack2(unsigned long long v) {
    float2 f;
    asm("mov.b64 {%0, %1}, %2;" : "=f"(f.x), "=f"(f.y) : "l"(v));
    return f;
}

// ---------------- K1: gather + time-encode -> fp16 A (no anony block) ----------------
// K layout: [0,172) src | [172,344) dst | [344,516) edge | [516,688) ts | [688,704) pad
__global__ void build_full_kernel(
    const int* __restrict__ nids, const int* __restrict__ hist_nids,
    const int* __restrict__ anon_ids, const int* __restrict__ hist_eids,
    const float* __restrict__ hist_ts, const int* __restrict__ hist_dirs,
    const float* __restrict__ node_emb, const float* __restrict__ edge_emb,
    const float* __restrict__ anony_emb, const float* __restrict__ time_w,
    const float* __restrict__ time_b, float* __restrict__ out_prevts)
{
    int row = blockIdx.x;
    int b = row / LH;
    int l = row - b * LH;
    int nid = nids[b];
    int hn  = hist_nids[row];
    int d   = hist_dirs[row];
    int src = d ? nid : hn;
    int dst = d ? hn  : nid;
    int aid = anon_ids[row];
    int eid = hist_eids[row];
    float tlast = hist_ts[b * LH + (LH - 1)];
    float dt = __fsub_rn(tlast, hist_ts[row]);
    bool last = (l == LH - 1);

    for (int j = threadIdx.x; j < KP2; j += blockDim.x) {
        float val = 0.0f;
        if (j < 172)      val = node_emb[(size_t)src * NFEAT + j];
        else if (j < 344) val = node_emb[(size_t)dst * NFEAT + (j - 172)];
        else if (j < 516) val = edge_emb[(size_t)eid * NFEAT + (j - 344)];
        else if (j < 688) {
            int jj = j - 516;
            float x = __fmul_rn(dt, time_w[jj]);
            x = __fadd_rn(x, time_b[jj]);
            val = cos_accurate(x);
        }
        if (last && j < 516) {
            // last_event_feat (original order: src, dst, anony, edge)
            int xo = (j < 344) ? (NFEAT + j) : (NFEAT + j + NFEAT);  // edge shifts past anony
            g_x[(size_t)b * DIM + xo] = val;
            val = 0.0f;
        }
        g_a[(size_t)row * KP2 + j] = __float2half_rn(val);
    }
    if (last) {
        for (int j = threadIdx.x; j < NFEAT; j += blockDim.x)
            g_x[(size_t)b * DIM + NFEAT + 344 + j] = anony_emb[(size_t)aid * NFEAT + j];
        if (threadIdx.x == 0) out_prevts[b] = tlast;
    }
}

// ---------------- K1b: in_proj_w (minus anony cols) -> padded fp16 ----------------
__global__ void split_b_kernel(const float* __restrict__ W)
{
    size_t idx = (size_t)blockIdx.x * blockDim.x + threadIdx.x;
    if (idx >= (size_t)NPAD2 * KP2) return;
    int r = (int)(idx / KP2);
    int k = (int)(idx - (size_t)r * KP2);
    float v = 0.0f;
    if (r < QKVN) {
        if (k < 344)      v = W[(size_t)r * DIM + k];
        else if (k < 688) v = W[(size_t)r * DIM + k + NFEAT];   // skip anony cols [344,516)
    }
    g_b[idx] = __float2half_rn(v);
}

// ---------------- K1c: AQ = anony_emb @ W[:,344:516]^T  (21 x 2580, fp32 exact) ----------------
__global__ void anony_proj_kernel(const float* __restrict__ anony_emb,
                                  const float* __restrict__ W)
{
    int n = blockIdx.x * blockDim.x + threadIdx.x;
    int a = blockIdx.y;
    if (n >= QKVN) return;
    float s = 0.0f;
    const float* wr = W + (size_t)n * DIM + 344;
    const float* ar = anony_emb + (size_t)a * NFEAT;
    #pragma unroll 4
    for (int k = 0; k < NFEAT; k++) s += ar[k] * wr[k];
    g_aq[(size_t)a * QKVN + n] = s;
}

// ---------------- K2: qkv GEMM via single-term fp16 mma.sync ----------------
// CTA tile 128x128, BK=64, 3-stage cp.async pipeline, 32KB/stage -> 2 CTAs/SM.
#define QSM_STAGE 32768
#define QSM_TOTAL (3*QSM_STAGE)

__device__ __forceinline__ void qkv_load_stage(
    uint32_t sb, int stage, int c, int bm, int bn, int tid,
    const __half* A, const __half* B)
{
    uint32_t sbase = sb + stage * QSM_STAGE;
    const size_t kof = (size_t)c * 64;
    #pragma unroll
    for (int it = 0; it < 4; it++) {
        int cid = tid + it * 256;          // 0..1023
        int r  = cid >> 3;
        int kc = cid & 7;
        uint32_t soff = (uint32_t)(r * 128 + ((kc ^ (r & 7)) << 4));
        const char* ga = (const char*)(A + (size_t)(bm + r) * KP2 + kof) + kc * 16;
        const char* gb = (const char*)(B + (size_t)(bn + r) * KP2 + kof) + kc * 16;
        cpa16(sbase +         soff, ga);
        cpa16(sbase + 16384 + soff, gb);
    }
    CP_COMMIT();
}

__global__ __launch_bounds__(256, 2) void qkv_mma_kernel(
    const __half* __restrict__ A, const __half* __restrict__ B,
    const float* __restrict__ bias, const float* __restrict__ AQ,
    const int* __restrict__ anon_ids, float* __restrict__ C)
{
    extern __shared__ char smem[];
    const uint32_t sb = smem_u32(smem);
    const int tid = threadIdx.x;
    const int wid = tid >> 5;
    const int lane = tid & 31;
    const int warp_m = wid >> 2;       // 0..1 -> 64 rows each
    const int warp_n = wid & 3;        // 0..3 -> 32 cols each
    const int bm = blockIdx.y * 128;
    const int bn = blockIdx.x * 128;

    float acc[4][4][4];
    #pragma unroll
    for (int mi = 0; mi < 4; mi++)
        #pragma unroll
        for (int nf = 0; nf < 4; nf++)
            #pragma unroll
            for (int t = 0; t < 4; t++) acc[mi][nf][t] = 0.0f;

    qkv_load_stage(sb, 0, 0, bm, bn, tid, A, B);
    qkv_load_stage(sb, 1, 1, bm, bn, tid, A, B);

    for (int c = 0; c < NC; c++) {
        const int stage = c % 3;
        CP_WAIT1();
        __syncthreads();
        if (c + 2 < NC)
            qkv_load_stage(sb, (c + 2) % 3, c + 2, bm, bn, tid, A, B);

        const uint32_t sA = sb + stage * QSM_STAGE;
        const uint32_t sB = sA + 16384;
        #pragma unroll
        for (int kk = 0; kk < 4; kk++) {
            uint32_t ah[4][4];
            #pragma unroll
            for (int mi = 0; mi < 4; mi++) {
                int mrow = warp_m * 64 + mi * 16 + (lane & 15);
                int chunk = kk * 2 + (lane >> 4);
                uint32_t addr = sA + mrow * 128 + ((chunk ^ (mrow & 7)) << 4);
                LDSM4(ah[mi], addr);
            }
            // B: NON-trans ldmatrix on [n][k] row-major smem.
            uint32_t bh[2][4];
            #pragma unroll
            for (int np = 0; np < 2; np++) {
                int nrow = warp_n * 32 + np * 16 + ((lane >> 4) << 3) + (lane & 7);
                int chunk = kk * 2 + ((lane >> 3) & 1);
                uint32_t addr = sB + nrow * 128 + ((chunk ^ (nrow & 7)) << 4);
                LDSM4(bh[np], addr);
            }
            #pragma unroll
            for (int mi = 0; mi < 4; mi++) {
                #pragma unroll
                for (int nf = 0; nf < 4; nf++) {
                    int np = nf >> 1, ri = (nf & 1) * 2;
                    MMA_F16(acc[mi][nf], ah[mi], bh[np][ri], bh[np][ri + 1]);
                }
            }
        }
    }

    // epilogue: + bias + anony gather (zero for last row of each sequence)
    const int group = lane >> 2;
    const int tc2 = (lane & 3) * 2;
    #pragma unroll
    for (int mi = 0; mi < 4; mi++) {
        int r0 = bm + warp_m * 64 + mi * 16 + group;
        int r1 = r0 + 8;
        int aid0 = anon_ids[r0];
        int aid1 = anon_ids[r1];
        bool nl0 = (r0 % LH) != (LH - 1);
        bool nl1 = (r1 % LH) != (LH - 1);
        #pragma unroll
        for (int nf = 0; nf < 4; nf++) {
            int n = bn + warp_n * 32 + nf * 8 + tc2;
            if (n >= QKVN) continue;
            float2 bv = *(const float2*)(bias + n);
            float2 o0, o1;
            o0.x = acc[mi][nf][0] + bv.x;
            o0.y = acc[mi][nf][1] + bv.y;
            o1.x = acc[mi][nf][2] + bv.x;
            o1.y = acc[mi][nf][3] + bv.y;
            if (nl0) {
                float2 q = *(const float2*)(AQ + (size_t)aid0 * QKVN + n);
                o0.x += q.x; o0.y += q.y;
            }
            if (nl1) {
                float2 q = *(const float2*)(AQ + (size_t)aid1 * QKVN + n);
                o1.x += q.x; o1.y += q.y;
            }
            *(float2*)(C + (size_t)r0 * QKVN + n) = o0;
            *(float2*)(C + (size_t)r1 * QKVN + n) = o1;
        }
    }
}

// ---------------- small-GEMM path (f32x2 SIMT) for K4-K7 ----------------
#define GBM 128
#define GBN 64
#define GBK 16

template<bool RELU_A, bool RELU_C>
__global__ __launch_bounds__(256) void gemm_nt(
    const float* __restrict__ A, int lda,
    const float* __restrict__ B, int ldb,
    const float* __restrict__ bias,
    float* __restrict__ C, int ldc,
    float* __restrict__ C2, int ldc2,
    int M, int N, int K)
{
    __shared__ float As[GBK][GBM + 4];
    __shared__ float Bs[GBK][GBN + 4];
    const int tid = threadIdx.x;
    const int tx = tid & 15;
    const int ty = tid >> 4;
    const int bm = blockIdx.y * GBM;
    const int bn = blockIdx.x * GBN;

    unsigned long long acc[4][4];
    #pragma unroll
    for (int p = 0; p < 4; p++)
        #pragma unroll
        for (int j = 0; j < 4; j++) acc[p][j] = 0ull;

    const int lr = tid >> 2;
    const int lc = (tid & 3) * 4;

    for (int k0 = 0; k0 < K; k0 += GBK) {
        #pragma unroll
        for (int r = 0; r < 2; r++) {
            int mrow = bm + lr + r * 64;
            float4 v = make_float4(0.f, 0.f, 0.f, 0.f);
            if (mrow < M && (k0 + lc) < K)
                v = *reinterpret_cast<const float4*>(A + (size_t)mrow * lda + k0 + lc);
            if (RELU_A) {
                v.x = fmaxf(v.x, 0.f); v.y = fmaxf(v.y, 0.f);
                v.z = fmaxf(v.z, 0.f); v.w = fmaxf(v.w, 0.f);
            }
            As[lc + 0][lr + r * 64] = v.x; As[lc + 1][lr + r * 64] = v.y;
            As[lc + 2][lr + r * 64] = v.z; As[lc + 3][lr + r * 64] = v.w;
        }
        {
            int nrow = bn + lr;
            float4 v = make_float4(0.f, 0.f, 0.f, 0.f);
            if (nrow < N && (k0 + lc) < K)
                v = *reinterpret_cast<const float4*>(B + (size_t)nrow * ldb + k0 + lc);
            Bs[lc + 0][lr] = v.x; Bs[lc + 1][lr] = v.y;
            Bs[lc + 2][lr] = v.z; Bs[lc + 3][lr] = v.w;
        }
        __syncthreads();
        #pragma unroll
        for (int kk = 0; kk < GBK; kk++) {
            const unsigned long long* ap =
                reinterpret_cast<const unsigned long long*>(&As[kk][ty * 8]);
            unsigned long long a0 = ap[0], a1 = ap[1], a2 = ap[2], a3 = ap[3];
            const float4 bq = *reinterpret_cast<const float4*>(&Bs[kk][tx * 4]);
            unsigned long long b0 = pack2(bq.x, bq.x), b1 = pack2(bq.y, bq.y);
            unsigned long long b2 = pack2(bq.z, bq.z), b3 = pack2(bq.w, bq.w);
            fma2(acc[0][0], a0, b0); fma2(acc[0][1], a0, b1); fma2(acc[0][2], a0, b2); fma2(acc[0][3], a0, b3);
            fma2(acc[1][0], a1, b0); fma2(acc[1][1], a1, b1); fma2(acc[1][2], a1, b2); fma2(acc[1][3], a1, b3);
            fma2(acc[2][0], a2, b0); fma2(acc[2][1], a2, b1); fma2(acc[2][2], a2, b2); fma2(acc[2][3], a2, b3);
            fma2(acc[3][0], a3, b0); fma2(acc[3][1], a3, b1); fma2(acc[3][2], a3, b2); fma2(acc[3][3], a3, b3);
        }
        __syncthreads();
    }

    #pragma unroll
    for (int j = 0; j < 4; j++) {
        int n = bn + tx * 4 + j;
        if (n >= N) continue;
        float bv = bias[n];
        #pragma unroll
        for (int p = 0; p < 4; p++) {
            float2 cc = unpack2(acc[p][j]);
            int m0 = bm + ty * 8 + 2 * p;
            float lo = cc.x + bv, hi = cc.y + bv;
            if (RELU_C) { lo = fmaxf(lo, 0.f); hi = fmaxf(hi, 0.f); }
            if (m0 < M) {
                C[(size_t)m0 * ldc + n] = lo;
                if (C2) C2[(size_t)m0 * ldc2 + n] = lo;
            }
            if (m0 + 1 < M) {
                C[(size_t)(m0 + 1) * ldc + n] = hi;
                if (C2) C2[(size_t)(m0 + 1) * ldc2 + n] = hi;
            }
        }
    }
}

// ---------------- K3: attention per (b, head) -> query-mean of ctx ----------------
#define SSTR 448
#define ATT_SMEM ((3*LH*SSTR + LH*LH + LH + 4) * 4)

__global__ __launch_bounds__(256) void attn_mean_kernel(
    const float* __restrict__ qkv, const int* __restrict__ hist_nids,
    float* __restrict__ ctx_mean)
{
    extern __shared__ float sm[];
    float* sq = sm;
    float* sk = sq + LH * SSTR;
    float* sv = sk + LH * SSTR;
    float* sc = sv + LH * SSTR;
    float* wb = sc + LH * LH;

    int b = blockIdx.x;
    int h = blockIdx.y;
    int tid = threadIdx.x;
    const float scale = (float)(1.0 / sqrt(430.0));

    size_t base = (size_t)b * LH * QKVN + (size_t)h * DHEAD;
    for (int idx = tid; idx < LH * SSTR; idx += 256) {
        int l = idx / SSTR, dd = idx - l * SSTR;
        float q = 0.f, k = 0.f, v = 0.f;
        if (dd < DHEAD) {
            size_t o = base + (size_t)l * QKVN + dd;
            q = qkv[o]; k = qkv[o + DIM]; v = qkv[o + 2 * DIM];
        }
        sq[idx] = q; sk[idx] = k; sv[idx] = v;
    }
    __syncthreads();

    int w = tid >> 5, lane = tid & 31;
    for (int qi = w; qi < LH; qi += 8) {
        float qreg[14];
        #pragma unroll
        for (int t = 0; t < 14; t++) qreg[t] = sq[qi * SSTR + lane + 32 * t];
        for (int ki = 0; ki < LH; ki++) {
            float s = 0.f;
            #pragma unroll
            for (int t = 0; t < 14; t++) s += qreg[t] * sk[ki * SSTR + lane + 32 * t];
            #pragma unroll
            for (int off = 16; off > 0; off >>= 1) s += __shfl_xor_sync(0xffffffffu, s, off);
            if (lane == 0) {
                int hn = hist_nids[b * LH + ki];
                bool masked = (hn == 0) && (ki != LH - 1);
                sc[qi * LH + ki] = masked ? -1e30f : s * scale;
            }
        }
    }
    __syncthreads();

    if (tid < LH) {
        int qi = tid;
        float mx = -1e30f;
        for (int ki = 0; ki < LH; ki++) mx = fmaxf(mx, sc[qi * LH + ki]);
        float sum = 0.f;
        for (int ki = 0; ki < LH; ki++) {
            float e = expf(sc[qi * LH + ki] - mx);
            sc[qi * LH + ki] = e;
            sum += e;
        }
        float inv = 1.f / sum;
        for (int ki = 0; ki < LH; ki++) sc[qi * LH + ki] *= inv;
    }
    __syncthreads();

    if (tid < LH) {
        int ki = tid;
        float s = 0.f;
        for (int qi = 0; qi < LH; qi++) s += sc[qi * LH + ki];
        wb[ki] = s * (1.0f / LH);
    }
    __syncthreads();

    for (int dd = tid; dd < DHEAD; dd += 256) {
        float s = 0.f;
        #pragma unroll
        for (int ki = 0; ki < LH; ki++) s += wb[ki] * sv[ki * SSTR + dd];
        ctx_mean[(size_t)b * DIM + (size_t)h * DHEAD + dd] = s;
    }
}

// ---------------- host ----------------
extern "C" void kernel_launch(void* const* d_in, const int* in_sizes, int n_in,
                              void* d_out, int out_size)
{
    const int*   nids       = (const int*)  d_in[0];
    const int*   hist_nids  = (const int*)  d_in[1];
    const int*   anon_ids   = (const int*)  d_in[2];
    const int*   hist_eids  = (const int*)  d_in[3];
    const float* hist_ts    = (const float*)d_in[4];
    const int*   hist_dirs  = (const int*)  d_in[5];
    const float* node_emb   = (const float*)d_in[6];
    const float* edge_emb   = (const float*)d_in[7];
    const float* anony_emb  = (const float*)d_in[8];
    const float* time_w     = (const float*)d_in[9];
    const float* time_b     = (const float*)d_in[10];
    const float* in_proj_w  = (const float*)d_in[11];
    const float* in_proj_b  = (const float*)d_in[12];
    const float* out_proj_w = (const float*)d_in[13];
    const float* out_proj_b = (const float*)d_in[14];
    const float* outfn_w    = (const float*)d_in[15];
    const float* outfn_b    = (const float*)d_in[16];
    const float* fc1_w      = (const float*)d_in[17];
    const float* fc1_b      = (const float*)d_in[18];
    const float* fc2_w      = (const float*)d_in[19];
    const float* fc2_b      = (const float*)d_in[20];

    float* out     = (float*)d_out;
    float* out_hl  = out;
    float* out_hr  = out + (size_t)BSZ * NFEAT;
    float* out_pts = out + (size_t)2 * BSZ * NFEAT;

    __half *a16, *b16;
    float *aq, *qkv, *cm, *mbuf, *xbuf, *hbuf;
    cudaGetSymbolAddress((void**)&a16, g_a);
    cudaGetSymbolAddress((void**)&b16, g_b);
    cudaGetSymbolAddress((void**)&aq,  g_aq);
    cudaGetSymbolAddress((void**)&qkv, g_qkv);
    cudaGetSymbolAddress((void**)&cm,  g_cm);
    cudaGetSymbolAddress((void**)&mbuf, g_m);
    cudaGetSymbolAddress((void**)&xbuf, g_x);
    cudaGetSymbolAddress((void**)&hbuf, g_h);

    cudaFuncSetAttribute(attn_mean_kernel,
                         cudaFuncAttributeMaxDynamicSharedMemorySize, ATT_SMEM);
    cudaFuncSetAttribute(qkv_mma_kernel,
                         cudaFuncAttributeMaxDynamicSharedMemorySize, QSM_TOTAL);

    // K1 family: build operands
    build_full_kernel<<<NROWS, 128>>>(nids, hist_nids, anon_ids, hist_eids, hist_ts,
                                      hist_dirs, node_emb, edge_emb, anony_emb,
                                      time_w, time_b, out_pts);
    {
        size_t tot = (size_t)NPAD2 * KP2;
        split_b_kernel<<<(int)((tot + 255) / 256), 256>>>(in_proj_w);
    }
    anony_proj_kernel<<<dim3((QKVN + 255) / 256, LH + 1), 256>>>(anony_emb, in_proj_w);

    // K2: qkv GEMM, single-term fp16 mma.sync
    {
        dim3 grid(NPAD2 / 128, NROWS / 128);
        qkv_mma_kernel<<<grid, 256, QSM_TOTAL>>>(a16, b16, in_proj_b, aq, anon_ids, qkv);
    }

    // K3: attention -> ctx mean over L
    attn_mean_kernel<<<dim3(BSZ, NHEAD), 256, ATT_SMEM>>>(qkv, hist_nids, cm);

    // K4: m = ctx_mean @ out_proj_w^T + b
    {
        dim3 grid((DIM + GBN - 1) / GBN, BSZ / GBM);
        gemm_nt<false, false><<<grid, 256>>>(cm, DIM, out_proj_w, DIM, out_proj_b,
                                             mbuf, DIM, (float*)nullptr, 0,
                                             BSZ, DIM, DIM);
    }
    // K5: hl = relu(m) @ outfn_w^T + b -> d_out AND x[:, :172]
    {
        dim3 grid((NFEAT + GBN - 1) / GBN, BSZ / GBM);
        gemm_nt<true, false><<<grid, 256>>>(mbuf, DIM, outfn_w, DIM, outfn_b,
                                            out_hl, NFEAT, xbuf, DIM,
                                            BSZ, NFEAT, DIM);
    }
    // K6: h = relu(x @ fc1_w^T + b)
    {
        dim3 grid((NFEAT + GBN - 1) / GBN, BSZ / GBM);
        gemm_nt<false, true><<<grid, 256>>>(xbuf, DIM, fc1_w, DIM, fc1_b,
                                            hbuf, NFEAT, (float*)nullptr, 0,
                                            BSZ, NFEAT, DIM);
    }
    // K7: hr = h @ fc2_w^T + b -> d_out
    {
        dim3 grid((NFEAT + GBN - 1) / GBN, BSZ / GBM);
        gemm_nt<false, false><<<grid, 256>>>(hbuf, NFEAT, fc2_w, NFEAT, fc2_b,
                                             out_hr, NFEAT, (float*)nullptr, 0,
                                             BSZ, NFEAT, NFEAT);
    }
}